// round 8
// baseline (speedup 1.0000x reference)
#include <cuda_runtime.h>
#include <cuda_fp16.h>
#include <cstdint>
#include <cstddef>

// y[n][o] = sum_r sum_m A[r][n][m] * Zt[r][o][m],  Zt = W_r @ X^T
// R=8, N=4096, F=128.
//
// stage1 (tf32 mma): Zt -> g_Zh fp16, chunk-contiguous [r][ch64][o][64].
// main  (fp16 m16n8k16): 64x128 CTA tile, 2 CTAs/SM, KC=64 chunks,
//        A converted fp32->fp16 in-flight, ldmatrix fragments.
// reduce: out = sum_r partial[r].

#define RREL 8
#define NN   4096
#define FF   128

// main-GEMM geometry
#define TN    64              // n rows per CTA
#define TO    128             // o cols per CTA (= FF)
#define KC2   64              // K per chunk
#define NCH2  (NN / KC2)      // 64 chunks
#define RW    72              // halves per smem row (64 + 8 pad) = 144B
#define ZSTG  3

// stage1 constants
#define S1S   68              // floats per smem row (64 + 4 pad)
#define S1CHF (128 * S1S)

// Scratch (allocation forbidden -> device globals)
__device__ __half g_Zh[(size_t)RREL * NCH2 * TO * KC2];   // 8MB fp16
__device__ float  g_partial[(size_t)RREL * NN * FF];      // 16MB

// ---------------------------------------------------------------------------
__device__ __forceinline__ uint32_t smem_to_u32(const void* p) {
    uint32_t a;
    asm("{ .reg .u64 t; cvta.to.shared.u64 t, %1; cvt.u32.u64 %0, t; }"
        : "=r"(a) : "l"(p));
    return a;
}

__device__ __forceinline__ uint32_t tf32_rna(float f) {
    uint32_t o;
    asm("cvt.rna.tf32.f32 %0, %1;" : "=r"(o) : "f"(f));
    return o;
}

// pack two fp32 into one fp16x2 register (lo = a, hi = b)
__device__ __forceinline__ uint32_t f16x2_rn(float a, float b) {
    uint32_t o;
    asm("cvt.rn.f16x2.f32 %0, %2, %1;" : "=r"(o) : "f"(a), "f"(b));
    return o;
}

__device__ __forceinline__ void mma_tf32(float d[4], const uint32_t a[4], const uint32_t b[2]) {
    asm volatile(
        "mma.sync.aligned.m16n8k8.row.col.f32.tf32.tf32.f32 "
        "{%0,%1,%2,%3}, {%4,%5,%6,%7}, {%8,%9}, {%0,%1,%2,%3};"
        : "+f"(d[0]), "+f"(d[1]), "+f"(d[2]), "+f"(d[3])
        : "r"(a[0]), "r"(a[1]), "r"(a[2]), "r"(a[3]), "r"(b[0]), "r"(b[1]));
}

__device__ __forceinline__ void mma_f16(float d[4], const uint32_t a[4], const uint32_t b[2]) {
    asm volatile(
        "mma.sync.aligned.m16n8k16.row.col.f32.f16.f16.f32 "
        "{%0,%1,%2,%3}, {%4,%5,%6,%7}, {%8,%9}, {%0,%1,%2,%3};"
        : "+f"(d[0]), "+f"(d[1]), "+f"(d[2]), "+f"(d[3])
        : "r"(a[0]), "r"(a[1]), "r"(a[2]), "r"(a[3]), "r"(b[0]), "r"(b[1]));
}

__device__ __forceinline__ void ldmatrix_x4(uint32_t r[4], uint32_t addr) {
    asm volatile("ldmatrix.sync.aligned.m8n8.x4.shared.b16 {%0,%1,%2,%3}, [%4];"
                 : "=r"(r[0]), "=r"(r[1]), "=r"(r[2]), "=r"(r[3]) : "r"(addr));
}

__device__ __forceinline__ void cp_async16(uint32_t smem_addr, const void* g) {
    asm volatile("cp.async.cg.shared.global [%0], [%1], 16;"
                 :: "r"(smem_addr), "l"(g) : "memory");
}
#define CP_COMMIT() asm volatile("cp.async.commit_group;" ::: "memory")
#define CP_WAIT(n)  asm volatile("cp.async.wait_group %0;" :: "n"(n) : "memory")

// ---------------------------------------------------------------------------
// Stage 1: g_Zh[r][m>>6][o][m&63] = fp16( sum_f W[r][o][f] * X[m][f] )
// Grid (32 m-tiles, 8 r), 256 threads, warp tile 64(o) x 32(m), tf32 mma.
// ---------------------------------------------------------------------------
#define S1_SMEM (2 * S1CHF * 4)   // 69632 bytes

__global__ __launch_bounds__(256, 1)
void rgcn_stage1(const float* __restrict__ X, const float* __restrict__ W) {
    extern __shared__ float smem[];
    float* ws = smem;
    float* xs = smem + S1CHF;

    int tid  = threadIdx.x;
    int wid  = tid >> 5;
    int lane = tid & 31;
    int gid  = lane >> 2;
    int tig  = lane & 3;
    int wm   = wid >> 2;          // 0..1 (o block of 64)
    int wn   = wid & 3;           // 0..3 (m block of 32)
    int m0   = blockIdx.x * 128;
    int r    = blockIdx.y;

    float acc[4][4][4];
    #pragma unroll
    for (int a = 0; a < 4; a++)
        #pragma unroll
        for (int b = 0; b < 4; b++)
            #pragma unroll
            for (int c = 0; c < 4; c++) acc[a][b][c] = 0.0f;

    for (int ch = 0; ch < 2; ch++) {
        __syncthreads();
        #pragma unroll
        for (int v = tid; v < 2048; v += 256) {
            int row = v >> 4, seg = v & 15;
            int soff = row * S1S + seg * 4;
            float4 w = *(const float4*)(W + ((size_t)r * FF + row) * FF + ch * 64 + seg * 4);
            w.x = __uint_as_float(tf32_rna(w.x)); w.y = __uint_as_float(tf32_rna(w.y));
            w.z = __uint_as_float(tf32_rna(w.z)); w.w = __uint_as_float(tf32_rna(w.w));
            *(float4*)(ws + soff) = w;
            float4 x = *(const float4*)(X + (size_t)(m0 + row) * FF + ch * 64 + seg * 4);
            x.x = __uint_as_float(tf32_rna(x.x)); x.y = __uint_as_float(tf32_rna(x.y));
            x.z = __uint_as_float(tf32_rna(x.z)); x.w = __uint_as_float(tf32_rna(x.w));
            *(float4*)(xs + soff) = x;
        }
        __syncthreads();

        #pragma unroll
        for (int ks = 0; ks < 8; ks++) {
            int k = ks * 8 + tig;
            uint32_t af[4][4], bf[4][2];
            #pragma unroll
            for (int mt = 0; mt < 4; mt++) {
                int roff = (wm * 64 + mt * 16 + gid) * S1S + k;
                af[mt][0] = __float_as_uint(ws[roff]);
                af[mt][1] = __float_as_uint(ws[roff + 8 * S1S]);
                af[mt][2] = __float_as_uint(ws[roff + 4]);
                af[mt][3] = __float_as_uint(ws[roff + 8 * S1S + 4]);
            }
            #pragma unroll
            for (int nt = 0; nt < 4; nt++) {
                int roff = (wn * 32 + nt * 8 + gid) * S1S + k;
                bf[nt][0] = __float_as_uint(xs[roff]);
                bf[nt][1] = __float_as_uint(xs[roff + 4]);
            }
            #pragma unroll
            for (int mt = 0; mt < 4; mt++)
                #pragma unroll
                for (int nt = 0; nt < 4; nt++)
                    mma_tf32(acc[mt][nt], af[mt], bf[nt]);
        }
    }

    // Epilogue: row = o, col = m; 64-wide chunk-contiguous fp16 layout.
    #pragma unroll
    for (int mt = 0; mt < 4; mt++)
        #pragma unroll
        for (int nt = 0; nt < 4; nt++) {
            int o = wm * 64 + mt * 16 + gid;
            int m = m0 + wn * 32 + nt * 8 + tig * 2;
            int ch = m >> 6, kc = m & 63;
            uint32_t* dst = (uint32_t*)(g_Zh + (((size_t)r * NCH2 + ch) * TO + o) * KC2 + kc);
            *dst = f16x2_rn(acc[mt][nt][0], acc[mt][nt][1]);
            uint32_t* dst2 = (uint32_t*)(g_Zh + (((size_t)r * NCH2 + ch) * TO + o + 8) * KC2 + kc);
            *dst2 = f16x2_rn(acc[mt][nt][2], acc[mt][nt][3]);
        }
}

// ---------------------------------------------------------------------------
// Main GEMM: partial[r][n][o] = sum_k A[r][n][k] * Zh[r][..][k]
// Grid (64 n-tiles, 8 r) = 512 CTAs, 256 threads, 2 CTAs/SM.
// Warp tile 32(n) x 32(o); KC=64 chunks; A double-buffer, Z 3-stage cp.async.
// ---------------------------------------------------------------------------
#define MG_SMEM ((2 * TN + ZSTG * TO) * RW * 2)   // (128+384)*72*2 = 73728 B

__global__ __launch_bounds__(256, 2)
void rgcn_main(const float* __restrict__ A) {
    extern __shared__ __half hsm[];
    __half* As = hsm;                       // [2][TN][RW]
    __half* Zs = hsm + 2 * TN * RW;         // [ZSTG][TO][RW]
    uint32_t as_u = smem_to_u32(As);
    uint32_t zs_u = smem_to_u32(Zs);
    const uint32_t A_STG_B = TN * RW * 2;   // 9216
    const uint32_t Z_STG_B = TO * RW * 2;   // 18432

    int tid  = threadIdx.x;
    int lane = tid & 31;
    int wid  = tid >> 5;
    int gid  = lane >> 2;
    int tig  = lane & 3;
    int wn   = wid & 1;                     // n block of 32
    int wo   = wid >> 1;                    // o block of 32 (0..3)
    int n0   = blockIdx.x * TN;
    int r    = blockIdx.y;

    const float*  Ab = A + ((size_t)r * NN + n0) * NN;
    const __half* Zb = g_Zh + (size_t)r * NCH2 * TO * KC2;

    // A producer: 16 consecutive floats per thread per chunk
    int arow = tid >> 2, aseg = tid & 3;
    const float* ag = Ab + (size_t)arow * NN + aseg * 16;
    uint32_t a_sts = as_u + (uint32_t)(arow * RW + aseg * 16) * 2;

    // Z producer: 64 contiguous bytes per thread per chunk (4 x cp.async16)
    int zrow = tid >> 1, zpart = tid & 1;
    const __half* zg = Zb + (size_t)zrow * KC2 + zpart * 32;
    uint32_t z_sts = zs_u + (uint32_t)(zrow * RW + zpart * 32) * 2;

    // ldmatrix per-lane base offsets (bytes within a stage)
    uint32_t a_lm = as_u + (uint32_t)((wn * 32 + (lane & 15)) * RW + (lane >> 4) * 8) * 2;
    uint32_t b_lm = zs_u + (uint32_t)((wo * 32 + (lane >> 4) * 8 + (lane & 7)) * RW
                                      + ((lane >> 3) & 1) * 8) * 2;

    float acc[2][4][4];
    #pragma unroll
    for (int a = 0; a < 2; a++)
        #pragma unroll
        for (int b = 0; b < 4; b++)
            #pragma unroll
            for (int c = 0; c < 4; c++) acc[a][b][c] = 0.0f;

    // Prologue: A chunk 0 -> regs; Z chunks 0,1 -> stages 0,1
    float4 c0 = *(const float4*)(ag);
    float4 c1 = *(const float4*)(ag + 4);
    float4 c2 = *(const float4*)(ag + 8);
    float4 c3 = *(const float4*)(ag + 12);
    #pragma unroll
    for (int c = 0; c < 2; c++) {
        #pragma unroll
        for (int j = 0; j < 4; j++)
            cp_async16(z_sts + c * Z_STG_B + j * 16, zg + (size_t)c * TO * KC2 + j * 8);
        CP_COMMIT();
    }

    for (int i = 0; i < NCH2; i++) {
        // STS A chunk i (fp32 regs -> fp16 smem), stage i&1
        {
            uint32_t st = a_sts + (i & 1) * A_STG_B;
            uint32_t h0 = f16x2_rn(c0.x, c0.y), h1 = f16x2_rn(c0.z, c0.w);
            uint32_t h2 = f16x2_rn(c1.x, c1.y), h3 = f16x2_rn(c1.z, c1.w);
            asm volatile("st.shared.v4.b32 [%0], {%1,%2,%3,%4};"
                         :: "r"(st), "r"(h0), "r"(h1), "r"(h2), "r"(h3) : "memory");
            uint32_t h4 = f16x2_rn(c2.x, c2.y), h5 = f16x2_rn(c2.z, c2.w);
            uint32_t h6 = f16x2_rn(c3.x, c3.y), h7 = f16x2_rn(c3.z, c3.w);
            asm volatile("st.shared.v4.b32 [%0], {%1,%2,%3,%4};"
                         :: "r"(st + 16), "r"(h4), "r"(h5), "r"(h6), "r"(h7) : "memory");
        }
        // LDG A chunk i+1 into regs (consumed next iter -> 1 chunk of latency)
        if (i + 1 < NCH2) {
            const float* p = ag + (size_t)(i + 1) * KC2;
            c0 = *(const float4*)(p);
            c1 = *(const float4*)(p + 4);
            c2 = *(const float4*)(p + 8);
            c3 = *(const float4*)(p + 12);
        }

        CP_WAIT(1);          // Z chunk i arrived
        __syncthreads();     // A STS visible; prior stage reads complete

        // cp.async Z chunk i+2 -> stage (i+2)%3 (consumed at iter i-1, free)
        if (i + 2 < NCH2) {
            const __half* src = zg + (size_t)(i + 2) * TO * KC2;
            uint32_t zd = z_sts + ((i + 2) % 3) * Z_STG_B;
            #pragma unroll
            for (int j = 0; j < 4; j++)
                cp_async16(zd + j * 16, src + j * 8);
        }
        CP_COMMIT();

        // Compute chunk i: 4 k-steps of 16
        uint32_t ab = a_lm + (i & 1) * A_STG_B;
        uint32_t bb = b_lm + (i % 3) * Z_STG_B;
        #pragma unroll
        for (int ks = 0; ks < 4; ks++) {
            uint32_t af[2][4], bf[4][2];
            #pragma unroll
            for (int mt = 0; mt < 2; mt++)
                ldmatrix_x4(af[mt], ab + (uint32_t)(mt * 16 * RW) * 2 + ks * 32);
            #pragma unroll
            for (int p = 0; p < 2; p++) {
                uint32_t br[4];
                ldmatrix_x4(br, bb + (uint32_t)(p * 16 * RW) * 2 + ks * 32);
                bf[2 * p][0] = br[0]; bf[2 * p][1] = br[1];
                bf[2 * p + 1][0] = br[2]; bf[2 * p + 1][1] = br[3];
            }
            #pragma unroll
            for (int mt = 0; mt < 2; mt++)
                #pragma unroll
                for (int ob = 0; ob < 4; ob++)
                    mma_f16(acc[mt][ob], af[mt], bf[ob]);
        }
    }

    // Epilogue: rows n, cols o
    #pragma unroll
    for (int mt = 0; mt < 2; mt++)
        #pragma unroll
        for (int ob = 0; ob < 4; ob++) {
            int n = n0 + wn * 32 + mt * 16 + gid;
            int o = wo * 32 + ob * 8 + tig * 2;
            float* dst = g_partial + ((size_t)r * NN + n) * FF + o;
            *(float2*)dst = make_float2(acc[mt][ob][0], acc[mt][ob][1]);
            *(float2*)(dst + 8 * FF) = make_float2(acc[mt][ob][2], acc[mt][ob][3]);
        }
}

// ---------------------------------------------------------------------------
// Reduce: out[n][o] = sum_r partial[r][n][o]
// ---------------------------------------------------------------------------
__global__ __launch_bounds__(256)
void rgcn_reduce(float* __restrict__ out) {
    int idx = blockIdx.x * 256 + threadIdx.x;          // float4 index (131072)
    const float4* p = (const float4*)g_partial;
    const int stride = NN * FF / 4;
    float4 acc = p[idx];
    #pragma unroll
    for (int s = 1; s < RREL; s++) {
        float4 t = p[(size_t)s * stride + idx];
        acc.x += t.x; acc.y += t.y; acc.z += t.z; acc.w += t.w;
    }
    ((float4*)out)[idx] = acc;
}

// ---------------------------------------------------------------------------
extern "C" void kernel_launch(void* const* d_in, const int* in_sizes, int n_in,
                              void* d_out, int out_size) {
    const float* A = (const float*)d_in[0];   // [8, 4096, 4096]
    const float* X = (const float*)d_in[1];   // [4096, 128]
    const float* W = (const float*)d_in[2];   // [8, 128, 128]
    float* out = (float*)d_out;               // [4096, 128]

    cudaFuncSetAttribute(rgcn_stage1, cudaFuncAttributeMaxDynamicSharedMemorySize, S1_SMEM);
    cudaFuncSetAttribute(rgcn_main,   cudaFuncAttributeMaxDynamicSharedMemorySize, MG_SMEM);

    rgcn_stage1<<<dim3(NN / 128, RREL), 256, S1_SMEM>>>(X, W);
    rgcn_main<<<dim3(NN / TN, RREL), 256, MG_SMEM>>>(A);
    rgcn_reduce<<<(NN * FF / 4) / 256, 256>>>(out);
}

// round 9
// speedup vs baseline: 1.0900x; 1.0900x over previous
#include <cuda_runtime.h>
#include <cuda_fp16.h>
#include <cstdint>
#include <cstddef>

// y[n][o] = sum_r sum_m A[r][n][m] * Zt[r][o][m],  Zt = W_r @ X^T
// R=8, N=4096, F=128.
//
// stage1 (tf32 mma): Zt -> g_Zh fp16, chunk-contiguous [r][ch64][o][64].
// main  (fp16 m16n8k16): 128x128 CTA tile, 512 thr, KC=64, 4-stage ring for
//        BOTH A (LDG+cvt+STS, distance 2) and Z (cp.async, distance 2);
//        per-iter critical path is bar -> ldsm -> mma only.
// reduce: out = sum_r partial[r].

#define RREL 8
#define NN   4096
#define FF   128

// main-GEMM geometry
#define TCTA  128             // n rows per CTA
#define TO    128             // o cols per CTA (= FF)
#define KC2   64              // K per chunk
#define NCH2  (NN / KC2)      // 64 chunks
#define RW    72              // halves per smem row (64 + 8 pad) = 144B
#define NSTG  4
#define STG_B (TCTA * RW * 2) // 18432 bytes per stage

// stage1 constants
#define S1S   68              // floats per smem row (64 + 4 pad)
#define S1CHF (128 * S1S)

// Scratch (allocation forbidden -> device globals)
__device__ __half g_Zh[(size_t)RREL * NCH2 * TO * KC2];   // 8MB fp16
__device__ float  g_partial[(size_t)RREL * NN * FF];      // 16MB

// ---------------------------------------------------------------------------
__device__ __forceinline__ uint32_t smem_to_u32(const void* p) {
    uint32_t a;
    asm("{ .reg .u64 t; cvta.to.shared.u64 t, %1; cvt.u32.u64 %0, t; }"
        : "=r"(a) : "l"(p));
    return a;
}

__device__ __forceinline__ uint32_t tf32_rna(float f) {
    uint32_t o;
    asm("cvt.rna.tf32.f32 %0, %1;" : "=r"(o) : "f"(f));
    return o;
}

// pack two fp32 into one fp16x2 register (lo = a, hi = b)
__device__ __forceinline__ uint32_t f16x2_rn(float a, float b) {
    uint32_t o;
    asm("cvt.rn.f16x2.f32 %0, %2, %1;" : "=r"(o) : "f"(a), "f"(b));
    return o;
}

__device__ __forceinline__ void mma_tf32(float d[4], const uint32_t a[4], const uint32_t b[2]) {
    asm volatile(
        "mma.sync.aligned.m16n8k8.row.col.f32.tf32.tf32.f32 "
        "{%0,%1,%2,%3}, {%4,%5,%6,%7}, {%8,%9}, {%0,%1,%2,%3};"
        : "+f"(d[0]), "+f"(d[1]), "+f"(d[2]), "+f"(d[3])
        : "r"(a[0]), "r"(a[1]), "r"(a[2]), "r"(a[3]), "r"(b[0]), "r"(b[1]));
}

__device__ __forceinline__ void mma_f16(float d[4], const uint32_t a[4], const uint32_t b[2]) {
    asm volatile(
        "mma.sync.aligned.m16n8k16.row.col.f32.f16.f16.f32 "
        "{%0,%1,%2,%3}, {%4,%5,%6,%7}, {%8,%9}, {%0,%1,%2,%3};"
        : "+f"(d[0]), "+f"(d[1]), "+f"(d[2]), "+f"(d[3])
        : "r"(a[0]), "r"(a[1]), "r"(a[2]), "r"(a[3]), "r"(b[0]), "r"(b[1]));
}

__device__ __forceinline__ void ldmatrix_x4(uint32_t r[4], uint32_t addr) {
    asm volatile("ldmatrix.sync.aligned.m8n8.x4.shared.b16 {%0,%1,%2,%3}, [%4];"
                 : "=r"(r[0]), "=r"(r[1]), "=r"(r[2]), "=r"(r[3]) : "r"(addr));
}

__device__ __forceinline__ void cp_async16(uint32_t smem_addr, const void* g) {
    asm volatile("cp.async.cg.shared.global [%0], [%1], 16;"
                 :: "r"(smem_addr), "l"(g) : "memory");
}
#define CP_COMMIT() asm volatile("cp.async.commit_group;" ::: "memory")
#define CP_WAIT(n)  asm volatile("cp.async.wait_group %0;" :: "n"(n) : "memory")

// ---------------------------------------------------------------------------
// Stage 1: g_Zh[r][m>>6][o][m&63] = fp16( sum_f W[r][o][f] * X[m][f] )
// Grid (32 m-tiles, 8 r), 256 threads, warp tile 64(o) x 32(m), tf32 mma.
// ---------------------------------------------------------------------------
#define S1_SMEM (2 * S1CHF * 4)   // 69632 bytes

__global__ __launch_bounds__(256, 1)
void rgcn_stage1(const float* __restrict__ X, const float* __restrict__ W) {
    extern __shared__ float smem[];
    float* ws = smem;
    float* xs = smem + S1CHF;

    int tid  = threadIdx.x;
    int wid  = tid >> 5;
    int lane = tid & 31;
    int gid  = lane >> 2;
    int tig  = lane & 3;
    int wm   = wid >> 2;          // 0..1 (o block of 64)
    int wn   = wid & 3;           // 0..3 (m block of 32)
    int m0   = blockIdx.x * 128;
    int r    = blockIdx.y;

    float acc[4][4][4];
    #pragma unroll
    for (int a = 0; a < 4; a++)
        #pragma unroll
        for (int b = 0; b < 4; b++)
            #pragma unroll
            for (int c = 0; c < 4; c++) acc[a][b][c] = 0.0f;

    for (int ch = 0; ch < 2; ch++) {
        __syncthreads();
        #pragma unroll
        for (int v = tid; v < 2048; v += 256) {
            int row = v >> 4, seg = v & 15;
            int soff = row * S1S + seg * 4;
            float4 w = *(const float4*)(W + ((size_t)r * FF + row) * FF + ch * 64 + seg * 4);
            w.x = __uint_as_float(tf32_rna(w.x)); w.y = __uint_as_float(tf32_rna(w.y));
            w.z = __uint_as_float(tf32_rna(w.z)); w.w = __uint_as_float(tf32_rna(w.w));
            *(float4*)(ws + soff) = w;
            float4 x = *(const float4*)(X + (size_t)(m0 + row) * FF + ch * 64 + seg * 4);
            x.x = __uint_as_float(tf32_rna(x.x)); x.y = __uint_as_float(tf32_rna(x.y));
            x.z = __uint_as_float(tf32_rna(x.z)); x.w = __uint_as_float(tf32_rna(x.w));
            *(float4*)(xs + soff) = x;
        }
        __syncthreads();

        #pragma unroll
        for (int ks = 0; ks < 8; ks++) {
            int k = ks * 8 + tig;
            uint32_t af[4][4], bf[4][2];
            #pragma unroll
            for (int mt = 0; mt < 4; mt++) {
                int roff = (wm * 64 + mt * 16 + gid) * S1S + k;
                af[mt][0] = __float_as_uint(ws[roff]);
                af[mt][1] = __float_as_uint(ws[roff + 8 * S1S]);
                af[mt][2] = __float_as_uint(ws[roff + 4]);
                af[mt][3] = __float_as_uint(ws[roff + 8 * S1S + 4]);
            }
            #pragma unroll
            for (int nt = 0; nt < 4; nt++) {
                int roff = (wn * 32 + nt * 8 + gid) * S1S + k;
                bf[nt][0] = __float_as_uint(xs[roff]);
                bf[nt][1] = __float_as_uint(xs[roff + 4]);
            }
            #pragma unroll
            for (int mt = 0; mt < 4; mt++)
                #pragma unroll
                for (int nt = 0; nt < 4; nt++)
                    mma_tf32(acc[mt][nt], af[mt], bf[nt]);
        }
    }

    // Epilogue: row = o, col = m; 64-wide chunk-contiguous fp16 layout.
    #pragma unroll
    for (int mt = 0; mt < 4; mt++)
        #pragma unroll
        for (int nt = 0; nt < 4; nt++) {
            int o = wm * 64 + mt * 16 + gid;
            int m = m0 + wn * 32 + nt * 8 + tig * 2;
            int ch = m >> 6, kc = m & 63;
            uint32_t* dst = (uint32_t*)(g_Zh + (((size_t)r * NCH2 + ch) * TO + o) * KC2 + kc);
            *dst = f16x2_rn(acc[mt][nt][0], acc[mt][nt][1]);
            uint32_t* dst2 = (uint32_t*)(g_Zh + (((size_t)r * NCH2 + ch) * TO + o + 8) * KC2 + kc);
            *dst2 = f16x2_rn(acc[mt][nt][2], acc[mt][nt][3]);
        }
}

// ---------------------------------------------------------------------------
// Main GEMM: partial[r][n][o] = sum_k A[r][n][k] * Zh[r][..][k]
// Grid (32 n-tiles, 8 r) = 256 CTAs, 512 threads, 1 CTA/SM.
// 4-stage ring, produce distance 2: at iter i fill chunk i+2, compute chunk i.
// ---------------------------------------------------------------------------
#define MG_SMEM (2 * NSTG * STG_B)   // 147456 bytes

__global__ __launch_bounds__(512, 1)
void rgcn_main(const float* __restrict__ A) {
    extern __shared__ __half hsm[];
    __half* As = hsm;                        // [NSTG][TCTA][RW]
    __half* Zs = hsm + NSTG * TCTA * RW;     // [NSTG][TO][RW]
    uint32_t as_u = smem_to_u32(As);
    uint32_t zs_u = smem_to_u32(Zs);

    int tid  = threadIdx.x;
    int lane = tid & 31;
    int wid  = tid >> 5;
    int gid  = lane >> 2;
    int tig  = lane & 3;
    int wn   = wid & 3;                      // n block of 32 (0..3)
    int wo   = wid >> 2;                     // o block of 32 (0..3)
    int n0   = blockIdx.x * TCTA;
    int r    = blockIdx.y;

    const float*  Ab = A + ((size_t)r * NN + n0) * NN;
    const __half* Zb = g_Zh + (size_t)r * NCH2 * TO * KC2;

    // Producer mapping (512 threads): row = tid>>2 (128 rows), seg = tid&3.
    // A: 16 consecutive floats per thread per chunk. Z: 32 bytes per thread.
    int prow = tid >> 2, pseg = tid & 3;
    const float*  ag = Ab + (size_t)prow * NN + pseg * 16;
    const __half* zg = Zb + (size_t)prow * KC2 + pseg * 16;
    uint32_t a_sts = as_u + (uint32_t)(prow * RW + pseg * 16) * 2;
    uint32_t z_sts = zs_u + (uint32_t)(prow * RW + pseg * 16) * 2;

    // ldmatrix per-lane base offsets (bytes within a stage)
    uint32_t a_lm = as_u + (uint32_t)((wn * 32 + (lane & 15)) * RW + (lane >> 4) * 8) * 2;
    uint32_t b_lm = zs_u + (uint32_t)((wo * 32 + (lane >> 4) * 8 + (lane & 7)) * RW
                                      + ((lane >> 3) & 1) * 8) * 2;

    float acc[2][4][4];
    #pragma unroll
    for (int a = 0; a < 2; a++)
        #pragma unroll
        for (int b = 0; b < 4; b++)
            #pragma unroll
            for (int c = 0; c < 4; c++) acc[a][b][c] = 0.0f;

    float4 c0, c1, c2, c3;
    #define LDA(ch) do { const float4* p = (const float4*)(ag + (size_t)(ch) * KC2); \
        c0 = p[0]; c1 = p[1]; c2 = p[2]; c3 = p[3]; } while (0)

    #define STSA(st) do { \
        uint32_t sa = a_sts + (uint32_t)(st) * STG_B; \
        uint32_t h0 = f16x2_rn(c0.x, c0.y), h1 = f16x2_rn(c0.z, c0.w); \
        uint32_t h2 = f16x2_rn(c1.x, c1.y), h3 = f16x2_rn(c1.z, c1.w); \
        asm volatile("st.shared.v4.b32 [%0], {%1,%2,%3,%4};" \
                     :: "r"(sa), "r"(h0), "r"(h1), "r"(h2), "r"(h3) : "memory"); \
        uint32_t h4 = f16x2_rn(c2.x, c2.y), h5 = f16x2_rn(c2.z, c2.w); \
        uint32_t h6 = f16x2_rn(c3.x, c3.y), h7 = f16x2_rn(c3.z, c3.w); \
        asm volatile("st.shared.v4.b32 [%0], {%1,%2,%3,%4};" \
                     :: "r"(sa + 16), "r"(h4), "r"(h5), "r"(h6), "r"(h7) : "memory"); \
    } while (0)

    #define CPZ(ch, st) do { \
        const __half* src = zg + (size_t)(ch) * TO * KC2; \
        uint32_t zd = z_sts + (uint32_t)(st) * STG_B; \
        cp_async16(zd, src); \
        cp_async16(zd + 16, src + 8); \
    } while (0)

    // Prologue: A chunks 0,1 -> smem stages 0,1; A chunk 2 -> regs;
    // Z chunks 0,1 -> stages 0,1 (one commit group each).
    LDA(0); STSA(0);
    LDA(1); STSA(1);
    LDA(2);
    CPZ(0, 0); CP_COMMIT();
    CPZ(1, 1); CP_COMMIT();

    for (int i = 0; i < NCH2; i++) {
        // Produce chunk i+2 (stage (i+2)&3): A from regs, Z via cp.async.
        STSA((i + 2) & 3);
        int jn = (i + 3 < NCH2) ? i + 3 : NCH2 - 1;   // clamp: dummy re-read
        LDA(jn);
        int jz = (i + 2 < NCH2) ? i + 2 : NCH2 - 1;
        CPZ(jz, (i + 2) & 3);
        CP_COMMIT();

        CP_WAIT(2);          // my Z group for chunk i complete
        __syncthreads();     // everyone's chunk-i data visible; stage reuse safe

        // Compute chunk i (data resident since iter i-2)
        uint32_t ab = a_lm + (uint32_t)(i & 3) * STG_B;
        uint32_t bb = b_lm + (uint32_t)(i & 3) * STG_B;
        #pragma unroll
        for (int ks = 0; ks < 4; ks++) {
            uint32_t af[2][4], bf[4][2];
            #pragma unroll
            for (int mt = 0; mt < 2; mt++)
                ldmatrix_x4(af[mt], ab + (uint32_t)(mt * 16 * RW) * 2 + ks * 32);
            #pragma unroll
            for (int p = 0; p < 2; p++) {
                uint32_t br[4];
                ldmatrix_x4(br, bb + (uint32_t)(p * 16 * RW) * 2 + ks * 32);
                bf[2 * p][0] = br[0]; bf[2 * p][1] = br[1];
                bf[2 * p + 1][0] = br[2]; bf[2 * p + 1][1] = br[3];
            }
            #pragma unroll
            for (int mt = 0; mt < 2; mt++)
                #pragma unroll
                for (int ob = 0; ob < 4; ob++)
                    mma_f16(acc[mt][ob], af[mt], bf[ob]);
        }
    }

    // Epilogue: rows n, cols o
    #pragma unroll
    for (int mt = 0; mt < 2; mt++)
        #pragma unroll
        for (int ob = 0; ob < 4; ob++) {
            int n = n0 + wn * 32 + mt * 16 + gid;
            int o = wo * 32 + ob * 8 + tig * 2;
            float* dst = g_partial + ((size_t)r * NN + n) * FF + o;
            *(float2*)dst = make_float2(acc[mt][ob][0], acc[mt][ob][1]);
            *(float2*)(dst + 8 * FF) = make_float2(acc[mt][ob][2], acc[mt][ob][3]);
        }
}

// ---------------------------------------------------------------------------
// Reduce: out[n][o] = sum_r partial[r][n][o]
// ---------------------------------------------------------------------------
__global__ __launch_bounds__(256)
void rgcn_reduce(float* __restrict__ out) {
    int idx = blockIdx.x * 256 + threadIdx.x;          // float4 index (131072)
    const float4* p = (const float4*)g_partial;
    const int stride = NN * FF / 4;
    float4 acc = p[idx];
    #pragma unroll
    for (int s = 1; s < RREL; s++) {
        float4 t = p[(size_t)s * stride + idx];
        acc.x += t.x; acc.y += t.y; acc.z += t.z; acc.w += t.w;
    }
    ((float4*)out)[idx] = acc;
}

// ---------------------------------------------------------------------------
extern "C" void kernel_launch(void* const* d_in, const int* in_sizes, int n_in,
                              void* d_out, int out_size) {
    const float* A = (const float*)d_in[0];   // [8, 4096, 4096]
    const float* X = (const float*)d_in[1];   // [4096, 128]
    const float* W = (const float*)d_in[2];   // [8, 128, 128]
    float* out = (float*)d_out;               // [4096, 128]

    cudaFuncSetAttribute(rgcn_stage1, cudaFuncAttributeMaxDynamicSharedMemorySize, S1_SMEM);
    cudaFuncSetAttribute(rgcn_main,   cudaFuncAttributeMaxDynamicSharedMemorySize, MG_SMEM);

    rgcn_stage1<<<dim3(NN / 128, RREL), 256, S1_SMEM>>>(X, W);
    rgcn_main<<<dim3(NN / TCTA, RREL), 512, MG_SMEM>>>(A);
    rgcn_reduce<<<(NN * FF / 4) / 256, 256>>>(out);
}

// round 11
// speedup vs baseline: 1.3555x; 1.2435x over previous
#include <cuda_runtime.h>
#include <cuda_fp16.h>
#include <cstdint>
#include <cstddef>

// y[n][o] = sum_r sum_m A[r][n][m] * Zt[r][o][m],  Zt = W_r @ X^T
// R=8, N=4096, F=128.
//
// stage1 (tf32 mma): Zt -> g_Zh fp16, chunk-contiguous [r][ch64][o][64].
// main  (fp16 m16n8k16): STREAM-K persistent kernel, 152 CTAs, global work
//        space = 256 tiles x 64 chunks; contiguous static partition; flush
//        accumulators per covered tile into per-(CTA,tile) segments.
// reduce: out[n][o] = sum over covering segments (closed-form), deterministic.

#define RREL 8
#define NN   4096
#define FF   128

// main-GEMM geometry
#define TCTA  128             // n rows per tile
#define TO    128             // o cols per tile (= FF)
#define KC2   64              // K per chunk
#define NCH2  (NN / KC2)      // 64 chunks per tile
#define RW    72              // halves per smem row (64 + 8 pad) = 144B
#define NSTG  4
#define STG_B (TCTA * RW * 2) // 18432 bytes per stage
#define NCTA  152             // persistent CTAs (GB300: 152 SMs)
#define NTILE 256             // 32 n-tiles x 8 relations
#define WTOT  (NTILE * NCH2)  // 16384 chunk-works

// stage1 constants
#define S1S   68              // floats per smem row (64 + 4 pad)
#define S1CHF (128 * S1S)

// Scratch (allocation forbidden -> device globals)
__device__ __half g_Zh[(size_t)RREL * NCH2 * TO * KC2];   // 8MB fp16
__device__ float  g_seg[(size_t)NCTA * 3 * TCTA * TO];    // 29.9MB segments

// ---------------------------------------------------------------------------
__device__ __forceinline__ uint32_t smem_to_u32(const void* p) {
    uint32_t a;
    asm("{ .reg .u64 t; cvta.to.shared.u64 t, %1; cvt.u32.u64 %0, t; }"
        : "=r"(a) : "l"(p));
    return a;
}

__device__ __forceinline__ uint32_t tf32_rna(float f) {
    uint32_t o;
    asm("cvt.rna.tf32.f32 %0, %1;" : "=r"(o) : "f"(f));
    return o;
}

// pack two fp32 into one fp16x2 register (lo = a, hi = b)
__device__ __forceinline__ uint32_t f16x2_rn(float a, float b) {
    uint32_t o;
    asm("cvt.rn.f16x2.f32 %0, %2, %1;" : "=r"(o) : "f"(a), "f"(b));
    return o;
}

__device__ __forceinline__ void mma_tf32(float d[4], const uint32_t a[4], const uint32_t b[2]) {
    asm volatile(
        "mma.sync.aligned.m16n8k8.row.col.f32.tf32.tf32.f32 "
        "{%0,%1,%2,%3}, {%4,%5,%6,%7}, {%8,%9}, {%0,%1,%2,%3};"
        : "+f"(d[0]), "+f"(d[1]), "+f"(d[2]), "+f"(d[3])
        : "r"(a[0]), "r"(a[1]), "r"(a[2]), "r"(a[3]), "r"(b[0]), "r"(b[1]));
}

__device__ __forceinline__ void mma_f16(float d[4], const uint32_t a[4], const uint32_t b[2]) {
    asm volatile(
        "mma.sync.aligned.m16n8k16.row.col.f32.f16.f16.f32 "
        "{%0,%1,%2,%3}, {%4,%5,%6,%7}, {%8,%9}, {%0,%1,%2,%3};"
        : "+f"(d[0]), "+f"(d[1]), "+f"(d[2]), "+f"(d[3])
        : "r"(a[0]), "r"(a[1]), "r"(a[2]), "r"(a[3]), "r"(b[0]), "r"(b[1]));
}

__device__ __forceinline__ void ldmatrix_x4(uint32_t r[4], uint32_t addr) {
    asm volatile("ldmatrix.sync.aligned.m8n8.x4.shared.b16 {%0,%1,%2,%3}, [%4];"
                 : "=r"(r[0]), "=r"(r[1]), "=r"(r[2]), "=r"(r[3]) : "r"(addr));
}

__device__ __forceinline__ void cp_async16(uint32_t smem_addr, const void* g) {
    asm volatile("cp.async.cg.shared.global [%0], [%1], 16;"
                 :: "r"(smem_addr), "l"(g) : "memory");
}
#define CP_COMMIT() asm volatile("cp.async.commit_group;" ::: "memory")
#define CP_WAIT(n)  asm volatile("cp.async.wait_group %0;" :: "n"(n) : "memory")

// profiling shim: shifts ncu's -s 5 capture onto rgcn_main
__global__ void knop() {}

// ---------------------------------------------------------------------------
// Stage 1: g_Zh[r][m>>6][o][m&63] = fp16( sum_f W[r][o][f] * X[m][f] )
// Grid (32 m-tiles, 8 r), 256 threads, warp tile 64(o) x 32(m), tf32 mma.
// ---------------------------------------------------------------------------
#define S1_SMEM (2 * S1CHF * 4)   // 69632 bytes

__global__ __launch_bounds__(256, 1)
void rgcn_stage1(const float* __restrict__ X, const float* __restrict__ W) {
    extern __shared__ float smem[];
    float* ws = smem;
    float* xs = smem + S1CHF;

    int tid  = threadIdx.x;
    int wid  = tid >> 5;
    int lane = tid & 31;
    int gid  = lane >> 2;
    int tig  = lane & 3;
    int wm   = wid >> 2;          // 0..1 (o block of 64)
    int wn   = wid & 3;           // 0..3 (m block of 32)
    int m0   = blockIdx.x * 128;
    int r    = blockIdx.y;

    float acc[4][4][4];
    #pragma unroll
    for (int a = 0; a < 4; a++)
        #pragma unroll
        for (int b = 0; b < 4; b++)
            #pragma unroll
            for (int c = 0; c < 4; c++) acc[a][b][c] = 0.0f;

    for (int ch = 0; ch < 2; ch++) {
        __syncthreads();
        #pragma unroll
        for (int v = tid; v < 2048; v += 256) {
            int row = v >> 4, seg = v & 15;
            int soff = row * S1S + seg * 4;
            float4 w = *(const float4*)(W + ((size_t)r * FF + row) * FF + ch * 64 + seg * 4);
            w.x = __uint_as_float(tf32_rna(w.x)); w.y = __uint_as_float(tf32_rna(w.y));
            w.z = __uint_as_float(tf32_rna(w.z)); w.w = __uint_as_float(tf32_rna(w.w));
            *(float4*)(ws + soff) = w;
            float4 x = *(const float4*)(X + (size_t)(m0 + row) * FF + ch * 64 + seg * 4);
            x.x = __uint_as_float(tf32_rna(x.x)); x.y = __uint_as_float(tf32_rna(x.y));
            x.z = __uint_as_float(tf32_rna(x.z)); x.w = __uint_as_float(tf32_rna(x.w));
            *(float4*)(xs + soff) = x;
        }
        __syncthreads();

        #pragma unroll
        for (int ks = 0; ks < 8; ks++) {
            int k = ks * 8 + tig;
            uint32_t af[4][4], bf[4][2];
            #pragma unroll
            for (int mt = 0; mt < 4; mt++) {
                int roff = (wm * 64 + mt * 16 + gid) * S1S + k;
                af[mt][0] = __float_as_uint(ws[roff]);
                af[mt][1] = __float_as_uint(ws[roff + 8 * S1S]);
                af[mt][2] = __float_as_uint(ws[roff + 4]);
                af[mt][3] = __float_as_uint(ws[roff + 8 * S1S + 4]);
            }
            #pragma unroll
            for (int nt = 0; nt < 4; nt++) {
                int roff = (wn * 32 + nt * 8 + gid) * S1S + k;
                bf[nt][0] = __float_as_uint(xs[roff]);
                bf[nt][1] = __float_as_uint(xs[roff + 4]);
            }
            #pragma unroll
            for (int mt = 0; mt < 4; mt++)
                #pragma unroll
                for (int nt = 0; nt < 4; nt++)
                    mma_tf32(acc[mt][nt], af[mt], bf[nt]);
        }
    }

    // Epilogue: row = o, col = m; 64-wide chunk-contiguous fp16 layout.
    #pragma unroll
    for (int mt = 0; mt < 4; mt++)
        #pragma unroll
        for (int nt = 0; nt < 4; nt++) {
            int o = wm * 64 + mt * 16 + gid;
            int m = m0 + wn * 32 + nt * 8 + tig * 2;
            int ch = m >> 6, kc = m & 63;
            uint32_t* dst = (uint32_t*)(g_Zh + (((size_t)r * NCH2 + ch) * TO + o) * KC2 + kc);
            *dst = f16x2_rn(acc[mt][nt][0], acc[mt][nt][1]);
            uint32_t* dst2 = (uint32_t*)(g_Zh + (((size_t)r * NCH2 + ch) * TO + o + 8) * KC2 + kc);
            *dst2 = f16x2_rn(acc[mt][nt][2], acc[mt][nt][3]);
        }
}

// ---------------------------------------------------------------------------
// Main GEMM, stream-K: work id w in [0, 16384), tile t = w>>6 (t = r*32+tn),
// chunk c = w&63. CTA b owns w with (w*NCTA)>>14 == b (contiguous ~108).
// 4-stage ring, produce distance 2. Flush accs per tile into
// g_seg[b*3 + (t - t0(b))].
// ---------------------------------------------------------------------------
#define MG_SMEM (2 * NSTG * STG_B)   // 147456 bytes

__global__ __launch_bounds__(512, 1)
void rgcn_main(const float* __restrict__ A) {
    extern __shared__ __half hsm[];
    __half* As = hsm;                        // [NSTG][TCTA][RW]
    __half* Zs = hsm + NSTG * TCTA * RW;     // [NSTG][TO][RW]
    uint32_t as_u = smem_to_u32(As);
    uint32_t zs_u = smem_to_u32(Zs);

    int tid  = threadIdx.x;
    int lane = tid & 31;
    int wid  = tid >> 5;
    int gid  = lane >> 2;
    int tig  = lane & 3;
    int wn   = wid & 3;                      // n block of 32 (0..3)
    int wo   = wid >> 2;                     // o block of 32 (0..3)
    int b    = blockIdx.x;

    uint32_t wbeg = (uint32_t)(b * WTOT + NCTA - 1) / NCTA;        // ceil
    uint32_t wend = (uint32_t)((b + 1) * WTOT + NCTA - 1) / NCTA;
    int t0 = (int)(wbeg >> 6);

    // Producer mapping (512 threads): row = tid>>2 (128 rows), seg = tid&3.
    int prow = tid >> 2, pseg = tid & 3;
    const float*  abase = A + (size_t)prow * NN + pseg * 16;       // + tile/chunk offsets
    const __half* zbase = g_Zh + (size_t)prow * KC2 + pseg * 16;
    uint32_t a_sts = as_u + (uint32_t)(prow * RW + pseg * 16) * 2;
    uint32_t z_sts = zs_u + (uint32_t)(prow * RW + pseg * 16) * 2;

    // ldmatrix per-lane base offsets (bytes within a stage)
    uint32_t a_lm = as_u + (uint32_t)((wn * 32 + (lane & 15)) * RW + (lane >> 4) * 8) * 2;
    uint32_t b_lm = zs_u + (uint32_t)((wo * 32 + (lane >> 4) * 8 + (lane & 7)) * RW
                                      + ((lane >> 3) & 1) * 8) * 2;

    float acc[2][4][4];
    #pragma unroll
    for (int a = 0; a < 2; a++)
        #pragma unroll
        for (int bb = 0; bb < 4; bb++)
            #pragma unroll
            for (int c = 0; c < 4; c++) acc[a][bb][c] = 0.0f;

    float4 c0, c1, c2, c3;
    // A address of work id ww for this thread
    #define AADDR(ww) (abase + ((size_t)((ww) >> 11) * NN            /* r * NN */ \
                       + (size_t)((((ww) >> 6) & 31) * TCTA)) * NN   /* tn*128 rows */ \
                       + ((ww) & 63) * KC2)                          /* chunk cols */
    #define ZADDR(ww) (zbase + ((size_t)((ww) >> 11) * NCH2 + ((ww) & 63)) * (TO * KC2))

    #define LDA_W(ww) do { const float4* p = (const float4*)AADDR(ww); \
        c0 = p[0]; c1 = p[1]; c2 = p[2]; c3 = p[3]; } while (0)

    #define STSA(st) do { \
        uint32_t sa = a_sts + (uint32_t)(st) * STG_B; \
        uint32_t h0 = f16x2_rn(c0.x, c0.y), h1 = f16x2_rn(c0.z, c0.w); \
        uint32_t h2 = f16x2_rn(c1.x, c1.y), h3 = f16x2_rn(c1.z, c1.w); \
        asm volatile("st.shared.v4.b32 [%0], {%1,%2,%3,%4};" \
                     :: "r"(sa), "r"(h0), "r"(h1), "r"(h2), "r"(h3) : "memory"); \
        uint32_t h4 = f16x2_rn(c2.x, c2.y), h5 = f16x2_rn(c2.z, c2.w); \
        uint32_t h6 = f16x2_rn(c3.x, c3.y), h7 = f16x2_rn(c3.z, c3.w); \
        asm volatile("st.shared.v4.b32 [%0], {%1,%2,%3,%4};" \
                     :: "r"(sa + 16), "r"(h4), "r"(h5), "r"(h6), "r"(h7) : "memory"); \
    } while (0)

    #define CPZ_W(ww, st) do { \
        const __half* src = ZADDR(ww); \
        uint32_t zd = z_sts + (uint32_t)(st) * STG_B; \
        cp_async16(zd, src); \
        cp_async16(zd + 16, src + 8); \
    } while (0)

    // Prologue (range size >= 64 always): chunks wbeg, wbeg+1 staged; wbeg+2 in regs
    LDA_W(wbeg);     STSA(wbeg & 3);
    LDA_W(wbeg + 1); STSA((wbeg + 1) & 3);
    LDA_W(wbeg + 2);
    CPZ_W(wbeg, wbeg & 3);           CP_COMMIT();
    CPZ_W(wbeg + 1, (wbeg + 1) & 3); CP_COMMIT();

    for (uint32_t w = wbeg; w < wend; ++w) {
        // Produce chunk w+2 (stage (w+2)&3)
        if (w + 2 < wend) {
            STSA((w + 2) & 3);
            uint32_t wl = (w + 3 < wend) ? w + 3 : wend - 1;
            LDA_W(wl);
            CPZ_W(w + 2, (w + 2) & 3);
        }
        CP_COMMIT();                  // one group per iter (possibly empty)

        CP_WAIT(2);                   // chunk w's Z group complete
        __syncthreads();              // chunk w visible; stage reuse safe

        // Compute chunk w (stage w&3)
        uint32_t ab = a_lm + (uint32_t)(w & 3) * STG_B;
        uint32_t bb = b_lm + (uint32_t)(w & 3) * STG_B;
        #pragma unroll
        for (int ks = 0; ks < 4; ks++) {
            uint32_t af[2][4], bf[4][2];
            #pragma unroll
            for (int mt = 0; mt < 2; mt++)
                ldmatrix_x4(af[mt], ab + (uint32_t)(mt * 16 * RW) * 2 + ks * 32);
            #pragma unroll
            for (int p = 0; p < 2; p++) {
                uint32_t br[4];
                ldmatrix_x4(br, bb + (uint32_t)(p * 16 * RW) * 2 + ks * 32);
                bf[2 * p][0] = br[0]; bf[2 * p][1] = br[1];
                bf[2 * p + 1][0] = br[2]; bf[2 * p + 1][1] = br[3];
            }
            #pragma unroll
            for (int mt = 0; mt < 2; mt++)
                #pragma unroll
                for (int ob = 0; ob < 4; ob++)
                    mma_f16(acc[mt][ob], af[mt], bf[ob]);
        }

        // Tile boundary: flush accumulators to this CTA's segment and reset
        if ((w & 63) == 63 || w + 1 == wend) {
            int t = (int)(w >> 6);
            float* segp = g_seg + ((size_t)b * 3 + (t - t0)) * (TCTA * TO);
            #pragma unroll
            for (int mt = 0; mt < 2; mt++)
                #pragma unroll
                for (int ob = 0; ob < 4; ob++) {
                    int nl = wn * 32 + mt * 16 + gid;
                    int o  = wo * 32 + ob * 8 + tig * 2;
                    float* dst = segp + (size_t)nl * TO + o;
                    *(float2*)dst = make_float2(acc[mt][ob][0], acc[mt][ob][1]);
                    *(float2*)(dst + 8 * TO) = make_float2(acc[mt][ob][2], acc[mt][ob][3]);
                    acc[mt][ob][0] = 0.0f; acc[mt][ob][1] = 0.0f;
                    acc[mt][ob][2] = 0.0f; acc[mt][ob][3] = 0.0f;
                }
        }
    }
}

// ---------------------------------------------------------------------------
// Reduce: out[n][o] = sum over r of sum over covering segments of tile
// t = r*32 + (n>>7). Covering CTAs: b in [(t*64*NCTA)>>14, ((t*64+63)*NCTA)>>14].
// ---------------------------------------------------------------------------
__global__ __launch_bounds__(256)
void rgcn_reduce(float* __restrict__ out) {
    int idx = blockIdx.x * 256 + threadIdx.x;   // float4 over [n][o]: 131072
    int n  = idx >> 5;                          // 32 float4 per 128-col row
    int o4 = idx & 31;
    int tn = n >> 7;
    int nl = n & 127;

    float4 acc = make_float4(0.f, 0.f, 0.f, 0.f);
    #pragma unroll
    for (int r = 0; r < RREL; r++) {
        int t   = r * 32 + tn;
        int blo = (t * 64 * NCTA) >> 14;
        int bhi = ((t * 64 + 63) * NCTA) >> 14;
        for (int b = blo; b <= bhi; b++) {
            int tb0 = (int)(((uint32_t)(b * WTOT + NCTA - 1) / NCTA) >> 6);
            const float4* sp = (const float4*)(g_seg
                + ((size_t)b * 3 + (t - tb0)) * (TCTA * TO));
            float4 v = sp[nl * (TO / 4) + o4];
            acc.x += v.x; acc.y += v.y; acc.z += v.z; acc.w += v.w;
        }
    }
    ((float4*)out)[idx] = acc;
}

// ---------------------------------------------------------------------------
extern "C" void kernel_launch(void* const* d_in, const int* in_sizes, int n_in,
                              void* d_out, int out_size) {
    const float* A = (const float*)d_in[0];   // [8, 4096, 4096]
    const float* X = (const float*)d_in[1];   // [4096, 128]
    const float* W = (const float*)d_in[2];   // [8, 128, 128]
    float* out = (float*)d_out;               // [4096, 128]

    cudaFuncSetAttribute(rgcn_stage1, cudaFuncAttributeMaxDynamicSharedMemorySize, S1_SMEM);
    cudaFuncSetAttribute(rgcn_main,   cudaFuncAttributeMaxDynamicSharedMemorySize, MG_SMEM);

    // two no-op launches: shifts ncu's "-s 5 -c 1" capture window onto rgcn_main
    knop<<<1, 32>>>();
    knop<<<1, 32>>>();
    rgcn_stage1<<<dim3(NN / 128, RREL), 256, S1_SMEM>>>(X, W);
    rgcn_main<<<NCTA, 512, MG_SMEM>>>(A);
    rgcn_reduce<<<(NN * FF / 4) / 256, 256>>>(out);
}